// round 5
// baseline (speedup 1.0000x reference)
#include <cuda_runtime.h>
#include <cuda_bf16.h>
#include <cstdint>
#include <math.h>

#define B_    16384
#define DIN   512
#define DH    1024

// K2 dims (tripled hi/lo split)
#define K2_S1 4608
#define K2_X  1536
#define K2_H  3072
#define N1    4096

// ---------------- scratch --------------------------------------------------
__device__ __nv_bfloat16 g_A2 [(size_t)B_ * K2_S1];   // [hi(h|x) | hi(h|x) | lo(h|x)]
__device__ __nv_bfloat16 g_W2 [(size_t)N1 * K2_S1];   // [hi | lo | hi] of 4 stacked gates
__device__ __nv_bfloat16 g_x2 [(size_t)B_ * K2_X];
__device__ __nv_bfloat16 g_Wx2[(size_t)DH * K2_X];
__device__ __nv_bfloat16 g_s2 [(size_t)B_ * K2_H];
__device__ __nv_bfloat16 g_rh2[(size_t)B_ * K2_H];
__device__ __nv_bfloat16 g_Ws2[(size_t)DH * K2_H];
__device__ __nv_bfloat16 g_Wh2[(size_t)DH * K2_H];
__device__ float g_C1   [(size_t)B_ * N1];    // only gates 1 (T) and 3 (z) written
__device__ float g_prehx[(size_t)B_ * DH];
__device__ float g_Tadd [(size_t)B_ * DH];

// ---------------- mma/ldmatrix/cp.async helpers -----------------------------
__device__ __forceinline__ uint32_t smem_u32(const void* p) {
    uint32_t a;
    asm("{ .reg .u64 t; cvta.to.shared.u64 t, %1; cvt.u32.u64 %0, t; }" : "=r"(a) : "l"(p));
    return a;
}
__device__ __forceinline__ void cp16(uint32_t sdst, const void* gsrc) {
    asm volatile("cp.async.cg.shared.global [%0], [%1], 16;" :: "r"(sdst), "l"(gsrc));
}
__device__ __forceinline__ void ldsm4(uint32_t* r, uint32_t addr) {
    asm volatile("ldmatrix.sync.aligned.m8n8.x4.shared.b16 {%0,%1,%2,%3}, [%4];"
                 : "=r"(r[0]), "=r"(r[1]), "=r"(r[2]), "=r"(r[3]) : "r"(addr));
}
__device__ __forceinline__ void mma16816(float* d, const uint32_t* a, uint32_t b0, uint32_t b1) {
    asm volatile("mma.sync.aligned.m16n8k16.row.col.f32.bf16.bf16.f32 "
                 "{%0,%1,%2,%3}, {%4,%5,%6,%7}, {%8,%9}, {%0,%1,%2,%3};"
                 : "+f"(d[0]), "+f"(d[1]), "+f"(d[2]), "+f"(d[3])
                 : "r"(a[0]), "r"(a[1]), "r"(a[2]), "r"(a[3]), "r"(b0), "r"(b1));
}

// ---------------- shared GEMM core: 128x256 CTA tile, 8 warps 2Mx4N ---------
// warp tile 64x64, BK=64 bf16 (128B SW128-style rows), 4-stage cp.async
#define NTHR 256
#define ST_A_BYTES (128 * 128)
#define ST_B_BYTES (256 * 128)
#define ST_STRIDE  (ST_A_BYTES + ST_B_BYTES)
#define STAGES 4
#define SM_TOT (STAGES * ST_STRIDE)      // 192 KB

__device__ __forceinline__ void load_tile(const __nv_bfloat16* __restrict__ A,
                                          const __nv_bfloat16* __restrict__ W,
                                          int K2, int m0, int n0,
                                          uint32_t sbase, int stage, int it, int tid)
{
    const size_t k0 = (size_t)it * 64;
    const uint32_t sA = sbase + stage * ST_STRIDE;
    const uint32_t sB = sA + ST_A_BYTES;
#pragma unroll
    for (int j = 0; j < 12; ++j) {
        int f = tid + j * NTHR;                  // 0..3071 (1024 A chunks, 2048 B chunks)
        if (f < 1024) {
            int row = f >> 3, c = f & 7;
            cp16(sA + row * 128 + ((c ^ (row & 7)) << 4),
                 A + (size_t)(m0 + row) * K2 + k0 + c * 8);
        } else {
            int f2 = f - 1024, row = f2 >> 3, c = f2 & 7;
            cp16(sB + row * 128 + ((c ^ (row & 7)) << 4),
                 W + (size_t)(n0 + row) * K2 + k0 + c * 8);
        }
    }
}

// acc[4][8][4]: mi (4 x m16), ni (8 x n8), frag
__device__ __forceinline__ void gemm_core(const __nv_bfloat16* __restrict__ A,
                                          const __nv_bfloat16* __restrict__ W,
                                          int K2, int m0, int n0,
                                          uint32_t sbase, int tid,
                                          float acc[4][8][4])
{
    const int wid = tid >> 5, lane = tid & 31;
    const int wm = (wid & 1) * 64;          // 2 warps in M
    const int wn = (wid >> 1) * 64;         // 4 warps in N
    const int T  = K2 >> 6;

#pragma unroll
    for (int i = 0; i < 4; i++)
#pragma unroll
        for (int j = 0; j < 8; j++)
#pragma unroll
            for (int k = 0; k < 4; k++) acc[i][j][k] = 0.f;

#pragma unroll
    for (int it = 0; it < STAGES - 1; ++it) {
        load_tile(A, W, K2, m0, n0, sbase, it, it, tid);
        asm volatile("cp.async.commit_group;" ::: "memory");
    }

    const int la = lane & 15;
    const int lk = lane >> 4;

    for (int it = 0; it < T; ++it) {
        asm volatile("cp.async.wait_group 2;" ::: "memory");
        __syncthreads();

        int pf = it + STAGES - 1;
        if (pf < T) load_tile(A, W, K2, m0, n0, sbase, pf % STAGES, pf, tid);
        asm volatile("cp.async.commit_group;" ::: "memory");

        const uint32_t aA = sbase + (it % STAGES) * ST_STRIDE;
        const uint32_t aB = aA + ST_A_BYTES;

#pragma unroll
        for (int ks = 0; ks < 4; ++ks) {
            const int c = ks * 2 + lk;
            uint32_t af[4][4];
#pragma unroll
            for (int mi = 0; mi < 4; ++mi) {
                int row = wm + mi * 16 + la;
                ldsm4(af[mi], aA + row * 128 + ((c ^ (row & 7)) << 4));
            }
            uint32_t bfr[4][4];
#pragma unroll
            for (int nb = 0; nb < 4; ++nb) {
                int row = wn + nb * 16 + la;
                ldsm4(bfr[nb], aB + row * 128 + ((c ^ (row & 7)) << 4));
            }
#pragma unroll
            for (int mi = 0; mi < 4; ++mi)
#pragma unroll
                for (int nb = 0; nb < 4; ++nb) {
                    mma16816(acc[mi][nb * 2 + 0], af[mi], bfr[nb][0], bfr[nb][2]);
                    mma16816(acc[mi][nb * 2 + 1], af[mi], bfr[nb][1], bfr[nb][3]);
                }
        }
    }
}

// ---------------- math helpers ---------------------------------------------
__device__ __forceinline__ float sigm(float x) { return 1.f / (1.f + expf(-x)); }
__device__ __forceinline__ void split2(float v, __nv_bfloat16& hi, __nv_bfloat16& lo) {
    hi = __float2bfloat16(v);
    lo = __float2bfloat16(v - __bfloat162float(hi));
}
__device__ __forceinline__ void store_split_pair(__nv_bfloat16* dst, size_t base,
                                                 float v0, float v1)
{
    __nv_bfloat16 h0, l0, h1, l1;
    split2(v0, h0, l0); split2(v1, h1, l1);
    __nv_bfloat162 hh; hh.x = h0; hh.y = h1;
    __nv_bfloat162 ll; ll.x = l0; ll.y = l1;
    *(__nv_bfloat162*)(dst + base)        = hh;
    *(__nv_bfloat162*)(dst + base + 1024) = hh;
    *(__nv_bfloat162*)(dst + base + 2048) = ll;
}

// ---------------- stage-1 GEMM with fused ew1 epilogue ----------------------
__global__ __launch_bounds__(NTHR, 1)
void gemm_s1_fused(const __nv_bfloat16* __restrict__ A, const __nv_bfloat16* __restrict__ W,
                   float* __restrict__ C,
                   const float* __restrict__ delta, const float* __restrict__ Wst,
                   const float* __restrict__ bs, const float* __restrict__ br,
                   const float* __restrict__ h)
{
    extern __shared__ __align__(1024) char smem[];
    const uint32_t sbase = smem_u32(smem);
    const int tid = threadIdx.x;
    const int m0 = blockIdx.y * 128;
    const int n0 = blockIdx.x * 256;

    float acc[4][8][4];
    gemm_core(A, W, K2_S1, m0, n0, sbase, tid, acc);

    const int wid = tid >> 5, lane = tid & 31;
    const int wm = (wid & 1) * 64;
    const int wn = (wid >> 1) * 64;
    const int gate = n0 >> 10;

#pragma unroll
    for (int mi = 0; mi < 4; ++mi) {
#pragma unroll
        for (int rr = 0; rr < 2; ++rr) {
            const int row = m0 + wm + mi * 16 + (lane >> 2) + rr * 8;
            const float dv = (gate == 0) ? delta[row] : 0.f;
#pragma unroll
            for (int ni = 0; ni < 8; ++ni) {
                const int colg = n0 + wn + ni * 8 + (lane & 3) * 2;
                const int ng   = colg & 1023;
                float v0 = acc[mi][ni][rr * 2 + 0];
                float v1 = acc[mi][ni][rr * 2 + 1];
                if (gate == 0) {
                    float s0 = tanhf(v0 + dv * Wst[ng]     + bs[ng]);
                    float s1 = tanhf(v1 + dv * Wst[ng + 1] + bs[ng + 1]);
                    store_split_pair(g_s2, (size_t)row * K2_H + ng, s0, s1);
                } else if (gate == 2) {
                    float r0 = sigm(v0 + br[ng])     * h[(size_t)row * DH + ng];
                    float r1 = sigm(v1 + br[ng + 1]) * h[(size_t)row * DH + ng + 1];
                    store_split_pair(g_rh2, (size_t)row * K2_H + ng, r0, r1);
                } else {
                    float2 v = { v0, v1 };
                    *(float2*)(C + (size_t)row * N1 + colg) = v;
                }
            }
        }
    }
}

// ---------------- plain GEMM (x-gemm, Tadd) ---------------------------------
__global__ __launch_bounds__(NTHR, 1)
void gemm_plain(const __nv_bfloat16* __restrict__ A, const __nv_bfloat16* __restrict__ W,
                float* __restrict__ C, int K2, int ldc)
{
    extern __shared__ __align__(1024) char smem[];
    const uint32_t sbase = smem_u32(smem);
    const int tid = threadIdx.x;
    const int m0 = blockIdx.y * 128;
    const int n0 = blockIdx.x * 256;

    float acc[4][8][4];
    gemm_core(A, W, K2, m0, n0, sbase, tid, acc);

    const int wid = tid >> 5, lane = tid & 31;
    const int wm = (wid & 1) * 64;
    const int wn = (wid >> 1) * 64;
#pragma unroll
    for (int mi = 0; mi < 4; ++mi) {
        int r0 = m0 + wm + mi * 16 + (lane >> 2);
#pragma unroll
        for (int ni = 0; ni < 8; ++ni) {
            int col = n0 + wn + ni * 8 + (lane & 3) * 2;
            float2 v0 = { acc[mi][ni][0], acc[mi][ni][1] };
            float2 v1 = { acc[mi][ni][2], acc[mi][ni][3] };
            *(float2*)(C + (size_t)r0 * ldc + col)       = v0;
            *(float2*)(C + (size_t)(r0 + 8) * ldc + col) = v1;
        }
    }
}

// ---------------- ht GEMM with fused ew2 epilogue ---------------------------
__global__ __launch_bounds__(NTHR, 1)
void gemm_ht_fused(const __nv_bfloat16* __restrict__ A, const __nv_bfloat16* __restrict__ W,
                   const float* __restrict__ bT, const float* __restrict__ bz,
                   const float* __restrict__ bb, const float* __restrict__ h,
                   float* __restrict__ out)
{
    extern __shared__ __align__(1024) char smem[];
    const uint32_t sbase = smem_u32(smem);
    const int tid = threadIdx.x;
    const int m0 = blockIdx.y * 128;
    const int n0 = blockIdx.x * 256;

    float acc[4][8][4];
    gemm_core(A, W, K2_H, m0, n0, sbase, tid, acc);

    const int wid = tid >> 5, lane = tid & 31;
    const int wm = (wid & 1) * 64;
    const int wn = (wid >> 1) * 64;

#pragma unroll
    for (int mi = 0; mi < 4; ++mi) {
#pragma unroll
        for (int rr = 0; rr < 2; ++rr) {
            const int row = m0 + wm + mi * 16 + (lane >> 2) + rr * 8;
#pragma unroll
            for (int ni = 0; ni < 8; ++ni) {
                const int ng = n0 + wn + ni * 8 + (lane & 3) * 2;
                const size_t e0 = (size_t)row * DH + ng;
                const size_t c0 = (size_t)row * N1 + ng;
                float v0 = acc[mi][ni][rr * 2 + 0];
                float v1 = acc[mi][ni][rr * 2 + 1];
                float T0 = sigm(g_C1[c0 + 1024]     + g_Tadd[e0]     + bT[ng]);
                float T1 = sigm(g_C1[c0 + 1025]     + g_Tadd[e0 + 1] + bT[ng + 1]);
                float z0 = sigm(g_C1[c0 + 3072]     + bz[ng]);
                float z1 = sigm(g_C1[c0 + 3073]     + bz[ng + 1]);
                float t0 = tanhf(v0 + g_prehx[e0]     + bb[ng]);
                float t1 = tanhf(v1 + g_prehx[e0 + 1] + bb[ng + 1]);
                float2 o;
                o.x = (1.f - z0) * (T0 * h[e0])     + z0 * t0;
                o.y = (1.f - z1) * (T1 * h[e0 + 1]) + z1 * t1;
                *(float2*)(out + e0) = o;
            }
        }
    }
}

// ---------------- fused conversion kernels ----------------------------------
#define NW2  (N1 * 1536)
#define NWX  (DH * DIN)
#define NWH  (DH * DH)
__global__ void convW_all(const float* __restrict__ Wsh, const float* __restrict__ Wsx,
                          const float* __restrict__ WTh, const float* __restrict__ WTx,
                          const float* __restrict__ Wrh, const float* __restrict__ Wrx,
                          const float* __restrict__ Wzh, const float* __restrict__ Wzx,
                          const float* __restrict__ Wx,  const float* __restrict__ WTs,
                          const float* __restrict__ Wh)
{
    int idx = blockIdx.x * blockDim.x + threadIdx.x;
    if (idx < NW2) {
        int n = idx / 1536, c = idx - n * 1536;
        int blk = n >> 10, r = n & (DH - 1);
        const float* Ph = (blk == 0) ? Wsh : (blk == 1) ? WTh : (blk == 2) ? Wrh : Wzh;
        const float* Px = (blk == 0) ? Wsx : (blk == 1) ? WTx : (blk == 2) ? Wrx : Wzx;
        float v = (c < DH) ? Ph[(size_t)r * DH + c] : Px[(size_t)r * DIN + c - DH];
        __nv_bfloat16 hi, lo; split2(v, hi, lo);
        size_t base = (size_t)n * K2_S1 + c;
        g_W2[base] = hi; g_W2[base + 1536] = lo; g_W2[base + 3072] = hi;
        return;
    }
    idx -= NW2;
    if (idx < NWX) {
        int n = idx / DIN, c = idx - n * DIN;
        __nv_bfloat16 hi, lo; split2(Wx[idx], hi, lo);
        size_t base = (size_t)n * K2_X + c;
        g_Wx2[base] = hi; g_Wx2[base + 512] = lo; g_Wx2[base + 1024] = hi;
        return;
    }
    idx -= NWX;
    if (idx < NWH) {
        int n = idx / DH, c = idx - n * DH;
        __nv_bfloat16 hi, lo; split2(WTs[idx], hi, lo);
        size_t base = (size_t)n * K2_H + c;
        g_Ws2[base] = hi; g_Ws2[base + 1024] = lo; g_Ws2[base + 2048] = hi;
        return;
    }
    idx -= NWH;
    if (idx < NWH) {
        int n = idx / DH, c = idx - n * DH;
        __nv_bfloat16 hi, lo; split2(Wh[idx], hi, lo);
        size_t base = (size_t)n * K2_H + c;
        g_Wh2[base] = hi; g_Wh2[base + 1024] = lo; g_Wh2[base + 2048] = hi;
    }
}
#define NW_ALL (NW2 + NWX + NWH + NWH)

#define NA2 (B_ * 1536)
#define NX2 (B_ * DIN)
__global__ void convAct(const float* __restrict__ h, const float* __restrict__ x)
{
    int idx = blockIdx.x * blockDim.x + threadIdx.x;
    if (idx < NA2) {
        int b = idx / 1536, c = idx - b * 1536;
        float v = (c < DH) ? h[(size_t)b * DH + c] : x[(size_t)b * DIN + c - DH];
        __nv_bfloat16 hi, lo; split2(v, hi, lo);
        size_t base = (size_t)b * K2_S1 + c;
        g_A2[base] = hi; g_A2[base + 1536] = hi; g_A2[base + 3072] = lo;
        return;
    }
    idx -= NA2;
    if (idx < NX2) {
        int b = idx / DIN, c = idx - b * DIN;
        __nv_bfloat16 hi, lo; split2(x[idx], hi, lo);
        size_t base = (size_t)b * K2_X + c;
        g_x2[base] = hi; g_x2[base + 512] = hi; g_x2[base + 1024] = lo;
    }
}
#define NACT (NA2 + NX2)

// ---------------- launch ----------------------------------------------------
extern "C" void kernel_launch(void* const* d_in, const int* in_sizes, int n_in,
                              void* d_out, int out_size)
{
    const float* x     = (const float*)d_in[0];
    const float* delta = (const float*)d_in[1];
    const float* h     = (const float*)d_in[2];
    const float* W_sh  = (const float*)d_in[3];
    const float* W_sx  = (const float*)d_in[4];
    const float* W_st  = (const float*)d_in[5];
    const float* b_s   = (const float*)d_in[6];
    const float* WTh   = (const float*)d_in[7];
    const float* WTx   = (const float*)d_in[8];
    const float* WTs   = (const float*)d_in[9];
    const float* b_T   = (const float*)d_in[10];
    const float* W_rh  = (const float*)d_in[11];
    const float* W_rx  = (const float*)d_in[12];
    const float* b_r   = (const float*)d_in[13];
    const float* W_zh  = (const float*)d_in[14];
    const float* W_zx  = (const float*)d_in[15];
    const float* b_z   = (const float*)d_in[16];
    const float* W_h   = (const float*)d_in[17];
    const float* W_x   = (const float*)d_in[18];
    const float* b     = (const float*)d_in[19];
    float* out = (float*)d_out;

    cudaFuncSetAttribute(gemm_s1_fused, cudaFuncAttributeMaxDynamicSharedMemorySize, SM_TOT);
    cudaFuncSetAttribute(gemm_plain,    cudaFuncAttributeMaxDynamicSharedMemorySize, SM_TOT);
    cudaFuncSetAttribute(gemm_ht_fused, cudaFuncAttributeMaxDynamicSharedMemorySize, SM_TOT);

    __nv_bfloat16 *dA2, *dW2, *dx2, *dWx2, *ds2, *drh2, *dWs2, *dWh2;
    float *dC1, *dprehx, *dTadd;
    cudaGetSymbolAddress((void**)&dA2,   g_A2);
    cudaGetSymbolAddress((void**)&dW2,   g_W2);
    cudaGetSymbolAddress((void**)&dx2,   g_x2);
    cudaGetSymbolAddress((void**)&dWx2,  g_Wx2);
    cudaGetSymbolAddress((void**)&ds2,   g_s2);
    cudaGetSymbolAddress((void**)&drh2,  g_rh2);
    cudaGetSymbolAddress((void**)&dWs2,  g_Ws2);
    cudaGetSymbolAddress((void**)&dWh2,  g_Wh2);
    cudaGetSymbolAddress((void**)&dC1,   g_C1);
    cudaGetSymbolAddress((void**)&dprehx,g_prehx);
    cudaGetSymbolAddress((void**)&dTadd, g_Tadd);

    // 1) conversions
    convW_all<<<(NW_ALL + 255) / 256, 256>>>(W_sh, W_sx, WTh, WTx, W_rh, W_rx,
                                             W_zh, W_zx, W_x, WTs, W_h);
    convAct  <<<(NACT + 255) / 256, 256>>>(h, x);

    // 2) stage-1 GEMM + fused ew1
    gemm_s1_fused<<<dim3(N1 / 256, B_ / 128), NTHR, SM_TOT>>>(
        dA2, dW2, dC1, delta, W_st, b_s, b_r, h);

    // 3) prehx = x2 @ Wx2^T
    gemm_plain<<<dim3(DH / 256, B_ / 128), NTHR, SM_TOT>>>(dx2, dWx2, dprehx, K2_X, DH);

    // 4) Tadd = s2 @ Ws2^T
    gemm_plain<<<dim3(DH / 256, B_ / 128), NTHR, SM_TOT>>>(ds2, dWs2, dTadd, K2_H, DH);

    // 5) ht GEMM + fused ew2 -> final output
    gemm_ht_fused<<<dim3(DH / 256, B_ / 128), NTHR, SM_TOT>>>(
        drh2, dWh2, b_T, b_z, b, h, out);
}

// round 6
// speedup vs baseline: 1.4979x; 1.4979x over previous
#include <cuda_runtime.h>
#include <cuda_bf16.h>
#include <cstdint>
#include <math.h>

#define B_    16384
#define DIN   512
#define DH    1024

// K2 dims (tripled hi/lo split)
#define K2_S1 4608
#define K2_X  1536
#define K2_H  3072
#define N1    4096

// ---------------- scratch --------------------------------------------------
__device__ __nv_bfloat16 g_A2 [(size_t)B_ * K2_S1];   // [hi(h|x) | hi(h|x) | lo(h|x)]
__device__ __nv_bfloat16 g_W2 [(size_t)N1 * K2_S1];   // [hi | lo | hi] of 4 stacked gates
__device__ __nv_bfloat16 g_x2 [(size_t)B_ * K2_X];
__device__ __nv_bfloat16 g_Wx2[(size_t)DH * K2_X];
__device__ __nv_bfloat16 g_s2 [(size_t)B_ * K2_H];
__device__ __nv_bfloat16 g_rh2[(size_t)B_ * K2_H];
__device__ __nv_bfloat16 g_Ws2[(size_t)DH * K2_H];
__device__ __nv_bfloat16 g_Wh2[(size_t)DH * K2_H];
__device__ float g_C1   [(size_t)B_ * N1];    // only gates 1 (T) and 3 (z) written
__device__ float g_prehx[(size_t)B_ * DH];
__device__ float g_Tadd [(size_t)B_ * DH];

// ---------------- mma/ldmatrix/cp.async helpers -----------------------------
__device__ __forceinline__ uint32_t smem_u32(const void* p) {
    uint32_t a;
    asm("{ .reg .u64 t; cvta.to.shared.u64 t, %1; cvt.u32.u64 %0, t; }" : "=r"(a) : "l"(p));
    return a;
}
__device__ __forceinline__ void cp16(uint32_t sdst, const void* gsrc) {
    asm volatile("cp.async.cg.shared.global [%0], [%1], 16;" :: "r"(sdst), "l"(gsrc));
}
__device__ __forceinline__ void ldsm4(uint32_t* r, uint32_t addr) {
    asm volatile("ldmatrix.sync.aligned.m8n8.x4.shared.b16 {%0,%1,%2,%3}, [%4];"
                 : "=r"(r[0]), "=r"(r[1]), "=r"(r[2]), "=r"(r[3]) : "r"(addr));
}
__device__ __forceinline__ void mma16816(float* d, const uint32_t* a, uint32_t b0, uint32_t b1) {
    asm volatile("mma.sync.aligned.m16n8k16.row.col.f32.bf16.bf16.f32 "
                 "{%0,%1,%2,%3}, {%4,%5,%6,%7}, {%8,%9}, {%0,%1,%2,%3};"
                 : "+f"(d[0]), "+f"(d[1]), "+f"(d[2]), "+f"(d[3])
                 : "r"(a[0]), "r"(a[1]), "r"(a[2]), "r"(a[3]), "r"(b0), "r"(b1));
}

// ---------------- shared GEMM core: 128x256 CTA tile, 8 warps 2Mx4N ---------
// warp tile 64x64, BK=64 bf16 (128B SW128-style rows), 4-stage cp.async
#define NTHR 256
#define ST_A_BYTES (128 * 128)
#define ST_B_BYTES (256 * 128)
#define ST_STRIDE  (ST_A_BYTES + ST_B_BYTES)
#define STAGES 4
#define SM_TOT (STAGES * ST_STRIDE)      // 192 KB

__device__ __forceinline__ void load_tile(const __nv_bfloat16* __restrict__ A,
                                          const __nv_bfloat16* __restrict__ W,
                                          int K2, int m0, int n0,
                                          uint32_t sbase, int stage, int it, int tid)
{
    const size_t k0 = (size_t)it * 64;
    const uint32_t sA = sbase + stage * ST_STRIDE;
    const uint32_t sB = sA + ST_A_BYTES;
#pragma unroll
    for (int j = 0; j < 12; ++j) {
        int f = tid + j * NTHR;                  // 0..3071 (1024 A chunks, 2048 B chunks)
        if (f < 1024) {
            int row = f >> 3, c = f & 7;
            cp16(sA + row * 128 + ((c ^ (row & 7)) << 4),
                 A + (size_t)(m0 + row) * K2 + k0 + c * 8);
        } else {
            int f2 = f - 1024, row = f2 >> 3, c = f2 & 7;
            cp16(sB + row * 128 + ((c ^ (row & 7)) << 4),
                 W + (size_t)(n0 + row) * K2 + k0 + c * 8);
        }
    }
}

// acc[4][8][4]: mi (4 x m16), ni (8 x n8), frag
__device__ __forceinline__ void gemm_core(const __nv_bfloat16* __restrict__ A,
                                          const __nv_bfloat16* __restrict__ W,
                                          int K2, int m0, int n0,
                                          uint32_t sbase, int tid,
                                          float acc[4][8][4])
{
    const int wid = tid >> 5, lane = tid & 31;
    const int wm = (wid & 1) * 64;          // 2 warps in M
    const int wn = (wid >> 1) * 64;         // 4 warps in N
    const int T  = K2 >> 6;

#pragma unroll
    for (int i = 0; i < 4; i++)
#pragma unroll
        for (int j = 0; j < 8; j++)
#pragma unroll
            for (int k = 0; k < 4; k++) acc[i][j][k] = 0.f;

#pragma unroll
    for (int it = 0; it < STAGES - 1; ++it) {
        load_tile(A, W, K2, m0, n0, sbase, it, it, tid);
        asm volatile("cp.async.commit_group;" ::: "memory");
    }

    const int la = lane & 15;
    const int lk = lane >> 4;

    for (int it = 0; it < T; ++it) {
        asm volatile("cp.async.wait_group 2;" ::: "memory");
        __syncthreads();

        int pf = it + STAGES - 1;
        if (pf < T) load_tile(A, W, K2, m0, n0, sbase, pf % STAGES, pf, tid);
        asm volatile("cp.async.commit_group;" ::: "memory");

        const uint32_t aA = sbase + (it % STAGES) * ST_STRIDE;
        const uint32_t aB = aA + ST_A_BYTES;

#pragma unroll
        for (int ks = 0; ks < 4; ++ks) {
            const int c = ks * 2 + lk;
            uint32_t af[4][4];
#pragma unroll
            for (int mi = 0; mi < 4; ++mi) {
                int row = wm + mi * 16 + la;
                ldsm4(af[mi], aA + row * 128 + ((c ^ (row & 7)) << 4));
            }
            uint32_t bfr[4][4];
#pragma unroll
            for (int nb = 0; nb < 4; ++nb) {
                int row = wn + nb * 16 + la;
                ldsm4(bfr[nb], aB + row * 128 + ((c ^ (row & 7)) << 4));
            }
#pragma unroll
            for (int mi = 0; mi < 4; ++mi)
#pragma unroll
                for (int nb = 0; nb < 4; ++nb) {
                    mma16816(acc[mi][nb * 2 + 0], af[mi], bfr[nb][0], bfr[nb][2]);
                    mma16816(acc[mi][nb * 2 + 1], af[mi], bfr[nb][1], bfr[nb][3]);
                }
        }
    }
}

// ---------------- math helpers ---------------------------------------------
__device__ __forceinline__ float sigm(float x) { return 1.f / (1.f + expf(-x)); }
__device__ __forceinline__ void split2(float v, __nv_bfloat16& hi, __nv_bfloat16& lo) {
    hi = __float2bfloat16(v);
    lo = __float2bfloat16(v - __bfloat162float(hi));
}
__device__ __forceinline__ void store_split_pair(__nv_bfloat16* dst, size_t base,
                                                 float v0, float v1)
{
    __nv_bfloat16 h0, l0, h1, l1;
    split2(v0, h0, l0); split2(v1, h1, l1);
    __nv_bfloat162 hh; hh.x = h0; hh.y = h1;
    __nv_bfloat162 ll; ll.x = l0; ll.y = l1;
    *(__nv_bfloat162*)(dst + base)        = hh;
    *(__nv_bfloat162*)(dst + base + 1024) = hh;
    *(__nv_bfloat162*)(dst + base + 2048) = ll;
}

// ---------------- stage-1 GEMM with fused ew1 epilogue ----------------------
__global__ __launch_bounds__(NTHR, 1)
void gemm_s1_fused(const __nv_bfloat16* __restrict__ A, const __nv_bfloat16* __restrict__ W,
                   float* __restrict__ C,
                   const float* __restrict__ delta, const float* __restrict__ Wst,
                   const float* __restrict__ bs, const float* __restrict__ br,
                   const float* __restrict__ h)
{
    extern __shared__ __align__(1024) char smem[];
    const uint32_t sbase = smem_u32(smem);
    const int tid = threadIdx.x;
    const int m0 = blockIdx.y * 128;
    const int n0 = blockIdx.x * 256;

    float acc[4][8][4];
    gemm_core(A, W, K2_S1, m0, n0, sbase, tid, acc);

    const int wid = tid >> 5, lane = tid & 31;
    const int wm = (wid & 1) * 64;
    const int wn = (wid >> 1) * 64;
    const int gate = n0 >> 10;

#pragma unroll
    for (int mi = 0; mi < 4; ++mi) {
#pragma unroll
        for (int rr = 0; rr < 2; ++rr) {
            const int row = m0 + wm + mi * 16 + (lane >> 2) + rr * 8;
            const float dv = (gate == 0) ? delta[row] : 0.f;
#pragma unroll
            for (int ni = 0; ni < 8; ++ni) {
                const int colg = n0 + wn + ni * 8 + (lane & 3) * 2;
                const int ng   = colg & 1023;
                float v0 = acc[mi][ni][rr * 2 + 0];
                float v1 = acc[mi][ni][rr * 2 + 1];
                if (gate == 0) {
                    float s0 = tanhf(v0 + dv * Wst[ng]     + bs[ng]);
                    float s1 = tanhf(v1 + dv * Wst[ng + 1] + bs[ng + 1]);
                    store_split_pair(g_s2, (size_t)row * K2_H + ng, s0, s1);
                } else if (gate == 2) {
                    float r0 = sigm(v0 + br[ng])     * h[(size_t)row * DH + ng];
                    float r1 = sigm(v1 + br[ng + 1]) * h[(size_t)row * DH + ng + 1];
                    store_split_pair(g_rh2, (size_t)row * K2_H + ng, r0, r1);
                } else {
                    float2 v = { v0, v1 };
                    *(float2*)(C + (size_t)row * N1 + colg) = v;
                }
            }
        }
    }
}

// ---------------- plain GEMM (x-gemm, Tadd) ---------------------------------
__global__ __launch_bounds__(NTHR, 1)
void gemm_plain(const __nv_bfloat16* __restrict__ A, const __nv_bfloat16* __restrict__ W,
                float* __restrict__ C, int K2, int ldc)
{
    extern __shared__ __align__(1024) char smem[];
    const uint32_t sbase = smem_u32(smem);
    const int tid = threadIdx.x;
    const int m0 = blockIdx.y * 128;
    const int n0 = blockIdx.x * 256;

    float acc[4][8][4];
    gemm_core(A, W, K2, m0, n0, sbase, tid, acc);

    const int wid = tid >> 5, lane = tid & 31;
    const int wm = (wid & 1) * 64;
    const int wn = (wid >> 1) * 64;
#pragma unroll
    for (int mi = 0; mi < 4; ++mi) {
        int r0 = m0 + wm + mi * 16 + (lane >> 2);
#pragma unroll
        for (int ni = 0; ni < 8; ++ni) {
            int col = n0 + wn + ni * 8 + (lane & 3) * 2;
            float2 v0 = { acc[mi][ni][0], acc[mi][ni][1] };
            float2 v1 = { acc[mi][ni][2], acc[mi][ni][3] };
            *(float2*)(C + (size_t)r0 * ldc + col)       = v0;
            *(float2*)(C + (size_t)(r0 + 8) * ldc + col) = v1;
        }
    }
}

// ---------------- ht GEMM with fused ew2 epilogue ---------------------------
__global__ __launch_bounds__(NTHR, 1)
void gemm_ht_fused(const __nv_bfloat16* __restrict__ A, const __nv_bfloat16* __restrict__ W,
                   const float* __restrict__ bT, const float* __restrict__ bz,
                   const float* __restrict__ bb, const float* __restrict__ h,
                   float* __restrict__ out)
{
    extern __shared__ __align__(1024) char smem[];
    const uint32_t sbase = smem_u32(smem);
    const int tid = threadIdx.x;
    const int m0 = blockIdx.y * 128;
    const int n0 = blockIdx.x * 256;

    float acc[4][8][4];
    gemm_core(A, W, K2_H, m0, n0, sbase, tid, acc);

    const int wid = tid >> 5, lane = tid & 31;
    const int wm = (wid & 1) * 64;
    const int wn = (wid >> 1) * 64;

#pragma unroll
    for (int mi = 0; mi < 4; ++mi) {
#pragma unroll
        for (int rr = 0; rr < 2; ++rr) {
            const int row = m0 + wm + mi * 16 + (lane >> 2) + rr * 8;
#pragma unroll
            for (int ni = 0; ni < 8; ++ni) {
                const int ng = n0 + wn + ni * 8 + (lane & 3) * 2;
                const size_t e0 = (size_t)row * DH + ng;
                const size_t c0 = (size_t)row * N1 + ng;
                float v0 = acc[mi][ni][rr * 2 + 0];
                float v1 = acc[mi][ni][rr * 2 + 1];
                float T0 = sigm(g_C1[c0 + 1024]     + g_Tadd[e0]     + bT[ng]);
                float T1 = sigm(g_C1[c0 + 1025]     + g_Tadd[e0 + 1] + bT[ng + 1]);
                float z0 = sigm(g_C1[c0 + 3072]     + bz[ng]);
                float z1 = sigm(g_C1[c0 + 3073]     + bz[ng + 1]);
                float t0 = tanhf(v0 + g_prehx[e0]     + bb[ng]);
                float t1 = tanhf(v1 + g_prehx[e0 + 1] + bb[ng + 1]);
                float2 o;
                o.x = (1.f - z0) * (T0 * h[e0])     + z0 * t0;
                o.y = (1.f - z1) * (T1 * h[e0 + 1]) + z1 * t1;
                *(float2*)(out + e0) = o;
            }
        }
    }
}

// ---------------- fused conversion kernels ----------------------------------
#define NW2  (N1 * 1536)
#define NWX  (DH * DIN)
#define NWH  (DH * DH)
__global__ void convW_all(const float* __restrict__ Wsh, const float* __restrict__ Wsx,
                          const float* __restrict__ WTh, const float* __restrict__ WTx,
                          const float* __restrict__ Wrh, const float* __restrict__ Wrx,
                          const float* __restrict__ Wzh, const float* __restrict__ Wzx,
                          const float* __restrict__ Wx,  const float* __restrict__ WTs,
                          const float* __restrict__ Wh)
{
    int idx = blockIdx.x * blockDim.x + threadIdx.x;
    if (idx < NW2) {
        int n = idx / 1536, c = idx - n * 1536;
        int blk = n >> 10, r = n & (DH - 1);
        const float* Ph = (blk == 0) ? Wsh : (blk == 1) ? WTh : (blk == 2) ? Wrh : Wzh;
        const float* Px = (blk == 0) ? Wsx : (blk == 1) ? WTx : (blk == 2) ? Wrx : Wzx;
        float v = (c < DH) ? Ph[(size_t)r * DH + c] : Px[(size_t)r * DIN + c - DH];
        __nv_bfloat16 hi, lo; split2(v, hi, lo);
        size_t base = (size_t)n * K2_S1 + c;
        g_W2[base] = hi; g_W2[base + 1536] = lo; g_W2[base + 3072] = hi;
        return;
    }
    idx -= NW2;
    if (idx < NWX) {
        int n = idx / DIN, c = idx - n * DIN;
        __nv_bfloat16 hi, lo; split2(Wx[idx], hi, lo);
        size_t base = (size_t)n * K2_X + c;
        g_Wx2[base] = hi; g_Wx2[base + 512] = lo; g_Wx2[base + 1024] = hi;
        return;
    }
    idx -= NWX;
    if (idx < NWH) {
        int n = idx / DH, c = idx - n * DH;
        __nv_bfloat16 hi, lo; split2(WTs[idx], hi, lo);
        size_t base = (size_t)n * K2_H + c;
        g_Ws2[base] = hi; g_Ws2[base + 1024] = lo; g_Ws2[base + 2048] = hi;
        return;
    }
    idx -= NWH;
    if (idx < NWH) {
        int n = idx / DH, c = idx - n * DH;
        __nv_bfloat16 hi, lo; split2(Wh[idx], hi, lo);
        size_t base = (size_t)n * K2_H + c;
        g_Wh2[base] = hi; g_Wh2[base + 1024] = lo; g_Wh2[base + 2048] = hi;
    }
}
#define NW_ALL (NW2 + NWX + NWH + NWH)

#define NA2 (B_ * 1536)
#define NX2 (B_ * DIN)
__global__ void convAct(const float* __restrict__ h, const float* __restrict__ x)
{
    int idx = blockIdx.x * blockDim.x + threadIdx.x;
    if (idx < NA2) {
        int b = idx / 1536, c = idx - b * 1536;
        float v = (c < DH) ? h[(size_t)b * DH + c] : x[(size_t)b * DIN + c - DH];
        __nv_bfloat16 hi, lo; split2(v, hi, lo);
        size_t base = (size_t)b * K2_S1 + c;
        g_A2[base] = hi; g_A2[base + 1536] = hi; g_A2[base + 3072] = lo;
        return;
    }
    idx -= NA2;
    if (idx < NX2) {
        int b = idx / DIN, c = idx - b * DIN;
        __nv_bfloat16 hi, lo; split2(x[idx], hi, lo);
        size_t base = (size_t)b * K2_X + c;
        g_x2[base] = hi; g_x2[base + 512] = hi; g_x2[base + 1024] = lo;
    }
}
#define NACT (NA2 + NX2)

// ---------------- launch ----------------------------------------------------
extern "C" void kernel_launch(void* const* d_in, const int* in_sizes, int n_in,
                              void* d_out, int out_size)
{
    const float* x     = (const float*)d_in[0];
    const float* delta = (const float*)d_in[1];
    const float* h     = (const float*)d_in[2];
    const float* W_sh  = (const float*)d_in[3];
    const float* W_sx  = (const float*)d_in[4];
    const float* W_st  = (const float*)d_in[5];
    const float* b_s   = (const float*)d_in[6];
    const float* WTh   = (const float*)d_in[7];
    const float* WTx   = (const float*)d_in[8];
    const float* WTs   = (const float*)d_in[9];
    const float* b_T   = (const float*)d_in[10];
    const float* W_rh  = (const float*)d_in[11];
    const float* W_rx  = (const float*)d_in[12];
    const float* b_r   = (const float*)d_in[13];
    const float* W_zh  = (const float*)d_in[14];
    const float* W_zx  = (const float*)d_in[15];
    const float* b_z   = (const float*)d_in[16];
    const float* W_h   = (const float*)d_in[17];
    const float* W_x   = (const float*)d_in[18];
    const float* b     = (const float*)d_in[19];
    float* out = (float*)d_out;

    cudaFuncSetAttribute(gemm_s1_fused, cudaFuncAttributeMaxDynamicSharedMemorySize, SM_TOT);
    cudaFuncSetAttribute(gemm_plain,    cudaFuncAttributeMaxDynamicSharedMemorySize, SM_TOT);
    cudaFuncSetAttribute(gemm_ht_fused, cudaFuncAttributeMaxDynamicSharedMemorySize, SM_TOT);

    __nv_bfloat16 *dA2, *dW2, *dx2, *dWx2, *ds2, *drh2, *dWs2, *dWh2;
    float *dC1, *dprehx, *dTadd;
    cudaGetSymbolAddress((void**)&dA2,   g_A2);
    cudaGetSymbolAddress((void**)&dW2,   g_W2);
    cudaGetSymbolAddress((void**)&dx2,   g_x2);
    cudaGetSymbolAddress((void**)&dWx2,  g_Wx2);
    cudaGetSymbolAddress((void**)&ds2,   g_s2);
    cudaGetSymbolAddress((void**)&drh2,  g_rh2);
    cudaGetSymbolAddress((void**)&dWs2,  g_Ws2);
    cudaGetSymbolAddress((void**)&dWh2,  g_Wh2);
    cudaGetSymbolAddress((void**)&dC1,   g_C1);
    cudaGetSymbolAddress((void**)&dprehx,g_prehx);
    cudaGetSymbolAddress((void**)&dTadd, g_Tadd);

    // 1) conversions
    convW_all<<<(NW_ALL + 255) / 256, 256>>>(W_sh, W_sx, WTh, WTx, W_rh, W_rx,
                                             W_zh, W_zx, W_x, WTs, W_h);
    convAct  <<<(NACT + 255) / 256, 256>>>(h, x);

    // 2) stage-1 GEMM + fused ew1
    gemm_s1_fused<<<dim3(N1 / 256, B_ / 128), NTHR, SM_TOT>>>(
        dA2, dW2, dC1, delta, W_st, b_s, b_r, h);

    // 3) prehx = x2 @ Wx2^T
    gemm_plain<<<dim3(DH / 256, B_ / 128), NTHR, SM_TOT>>>(dx2, dWx2, dprehx, K2_X, DH);

    // 4) Tadd = s2 @ Ws2^T
    gemm_plain<<<dim3(DH / 256, B_ / 128), NTHR, SM_TOT>>>(ds2, dWs2, dTadd, K2_H, DH);

    // 5) ht GEMM + fused ew2 -> final output
    gemm_ht_fused<<<dim3(DH / 256, B_ / 128), NTHR, SM_TOT>>>(
        drh2, dWh2, b_T, b_z, b, h, out);
}

// round 7
// speedup vs baseline: 1.6065x; 1.0725x over previous
#include <cuda_runtime.h>
#include <cuda_fp16.h>
#include <cstdint>
#include <math.h>

#define B_    16384
#define DIN   512
#define DH    1024

// 2-term fp16 split K dims
#define K2_S1 3072    // [h_hi|h_lo|x_hi|x_lo]
#define K2_H  2048    // [s_hi|s_lo]
#define K2_HT 3072    // [rh_hi|rh_lo|x_hi|x_lo]
#define N1    4096

// ---------------- scratch --------------------------------------------------
__device__ __half g_A2 [(size_t)B_ * K2_S1];
__device__ __half g_W2 [(size_t)N1 * K2_S1];
__device__ __half g_s2 [(size_t)B_ * K2_H];
__device__ __half g_Ws2[(size_t)DH * K2_H];
__device__ __half g_Aht[(size_t)B_ * K2_HT];
__device__ __half g_Wht[(size_t)DH * K2_HT];
__device__ float  g_C1  [(size_t)B_ * N1];    // only gates 1 (T) and 3 (z) written
__device__ float  g_Tadd[(size_t)B_ * DH];

// ---------------- mma/ldmatrix/cp.async helpers -----------------------------
__device__ __forceinline__ uint32_t smem_u32(const void* p) {
    uint32_t a;
    asm("{ .reg .u64 t; cvta.to.shared.u64 t, %1; cvt.u32.u64 %0, t; }" : "=r"(a) : "l"(p));
    return a;
}
__device__ __forceinline__ void cp16(uint32_t sdst, const void* gsrc) {
    asm volatile("cp.async.cg.shared.global [%0], [%1], 16;" :: "r"(sdst), "l"(gsrc));
}
__device__ __forceinline__ void ldsm4(uint32_t* r, uint32_t addr) {
    asm volatile("ldmatrix.sync.aligned.m8n8.x4.shared.b16 {%0,%1,%2,%3}, [%4];"
                 : "=r"(r[0]), "=r"(r[1]), "=r"(r[2]), "=r"(r[3]) : "r"(addr));
}
__device__ __forceinline__ void mma16816(float* d, const uint32_t* a, uint32_t b0, uint32_t b1) {
    asm volatile("mma.sync.aligned.m16n8k16.row.col.f32.f16.f16.f32 "
                 "{%0,%1,%2,%3}, {%4,%5,%6,%7}, {%8,%9}, {%0,%1,%2,%3};"
                 : "+f"(d[0]), "+f"(d[1]), "+f"(d[2]), "+f"(d[3])
                 : "r"(a[0]), "r"(a[1]), "r"(a[2]), "r"(a[3]), "r"(b0), "r"(b1));
}

// ---------------- GEMM core (R4 config): 128x256 CTA, 512 thr, 4Mx4N warps --
#define NTHR 512
#define ST_A_BYTES (128 * 128)
#define ST_B_BYTES (256 * 128)
#define ST_STRIDE  (ST_A_BYTES + ST_B_BYTES)
#define STAGES 3
#define SM_TOT (STAGES * ST_STRIDE)      // 144 KB

__device__ __forceinline__ void load_tile(const __half* __restrict__ A,
                                          const __half* __restrict__ W,
                                          int K2, int m0, int n0,
                                          uint32_t sbase, int stage, int it, int tid)
{
    const size_t k0 = (size_t)it * 64;
    const uint32_t sA = sbase + stage * ST_STRIDE;
    const uint32_t sB = sA + ST_A_BYTES;
#pragma unroll
    for (int j = 0; j < 6; ++j) {
        int f = tid + j * NTHR;
        if (f < 1024) {
            int row = f >> 3, c = f & 7;
            cp16(sA + row * 128 + ((c ^ (row & 7)) << 4),
                 A + (size_t)(m0 + row) * K2 + k0 + c * 8);
        } else {
            int f2 = f - 1024, row = f2 >> 3, c = f2 & 7;
            cp16(sB + row * 128 + ((c ^ (row & 7)) << 4),
                 W + (size_t)(n0 + row) * K2 + k0 + c * 8);
        }
    }
}

__device__ __forceinline__ void gemm_core(const __half* __restrict__ A,
                                          const __half* __restrict__ W,
                                          int K2, int m0, int n0,
                                          uint32_t sbase, int tid,
                                          float acc[2][8][4])
{
    const int wid = tid >> 5, lane = tid & 31;
    const int wm = (wid & 3) * 32;
    const int wn = (wid >> 2) * 64;
    const int T  = K2 >> 6;

#pragma unroll
    for (int i = 0; i < 2; i++)
#pragma unroll
        for (int j = 0; j < 8; j++)
#pragma unroll
            for (int k = 0; k < 4; k++) acc[i][j][k] = 0.f;

#pragma unroll
    for (int it = 0; it < STAGES - 1; ++it) {
        load_tile(A, W, K2, m0, n0, sbase, it, it, tid);
        asm volatile("cp.async.commit_group;" ::: "memory");
    }

    const int la = lane & 15;
    const int lk = lane >> 4;

    for (int it = 0; it < T; ++it) {
        asm volatile("cp.async.wait_group 1;" ::: "memory");
        __syncthreads();

        int pf = it + STAGES - 1;
        if (pf < T) load_tile(A, W, K2, m0, n0, sbase, pf % STAGES, pf, tid);
        asm volatile("cp.async.commit_group;" ::: "memory");

        const uint32_t aA = sbase + (it % STAGES) * ST_STRIDE;
        const uint32_t aB = aA + ST_A_BYTES;

#pragma unroll
        for (int ks = 0; ks < 4; ++ks) {
            const int c = ks * 2 + lk;
            uint32_t af[2][4];
#pragma unroll
            for (int mi = 0; mi < 2; ++mi) {
                int row = wm + mi * 16 + la;
                ldsm4(af[mi], aA + row * 128 + ((c ^ (row & 7)) << 4));
            }
            uint32_t bfr[4][4];
#pragma unroll
            for (int nb = 0; nb < 4; ++nb) {
                int row = wn + nb * 16 + la;
                ldsm4(bfr[nb], aB + row * 128 + ((c ^ (row & 7)) << 4));
            }
#pragma unroll
            for (int mi = 0; mi < 2; ++mi)
#pragma unroll
                for (int nb = 0; nb < 4; ++nb) {
                    mma16816(acc[mi][nb * 2 + 0], af[mi], bfr[nb][0], bfr[nb][2]);
                    mma16816(acc[mi][nb * 2 + 1], af[mi], bfr[nb][1], bfr[nb][3]);
                }
        }
    }
}

// ---------------- math helpers ---------------------------------------------
__device__ __forceinline__ float sigm(float x) { return 1.f / (1.f + expf(-x)); }
__device__ __forceinline__ void split2h(float v, __half& hi, __half& lo) {
    hi = __float2half(v);
    lo = __float2half(v - __half2float(hi));
}
// store [hi|lo] pair-of-columns into a K-split buffer (stride 1024 between hi/lo)
__device__ __forceinline__ void store_split_pair(__half* dst, size_t base,
                                                 float v0, float v1)
{
    __half h0, l0, h1, l1;
    split2h(v0, h0, l0); split2h(v1, h1, l1);
    __half2 hh; hh.x = h0; hh.y = h1;
    __half2 ll; ll.x = l0; ll.y = l1;
    *(__half2*)(dst + base)        = hh;
    *(__half2*)(dst + base + 1024) = ll;
}

// ---------------- stage-1 GEMM with fused ew1 epilogue ----------------------
// gate = n0>>10: 0 -> s_t (g_s2), 1 -> C1, 2 -> r*h (g_Aht[0:2048]), 3 -> C1
__global__ __launch_bounds__(NTHR)
void gemm_s1_fused(const __half* __restrict__ A, const __half* __restrict__ W,
                   float* __restrict__ C,
                   const float* __restrict__ delta, const float* __restrict__ Wst,
                   const float* __restrict__ bs, const float* __restrict__ br,
                   const float* __restrict__ h)
{
    extern __shared__ __align__(1024) char smem[];
    const uint32_t sbase = smem_u32(smem);
    const int tid = threadIdx.x;
    const int m0 = blockIdx.y * 128;
    const int n0 = blockIdx.x * 256;

    float acc[2][8][4];
    gemm_core(A, W, K2_S1, m0, n0, sbase, tid, acc);

    const int wid = tid >> 5, lane = tid & 31;
    const int wm = (wid & 3) * 32;
    const int wn = (wid >> 2) * 64;
    const int gate = n0 >> 10;

#pragma unroll
    for (int mi = 0; mi < 2; ++mi) {
#pragma unroll
        for (int rr = 0; rr < 2; ++rr) {
            const int row = m0 + wm + mi * 16 + (lane >> 2) + rr * 8;
            const float dv = (gate == 0) ? delta[row] : 0.f;
#pragma unroll
            for (int ni = 0; ni < 8; ++ni) {
                const int colg = n0 + wn + ni * 8 + (lane & 3) * 2;
                const int ng   = colg & 1023;
                float v0 = acc[mi][ni][rr * 2 + 0];
                float v1 = acc[mi][ni][rr * 2 + 1];
                if (gate == 0) {
                    float s0 = tanhf(v0 + dv * Wst[ng]     + bs[ng]);
                    float s1 = tanhf(v1 + dv * Wst[ng + 1] + bs[ng + 1]);
                    store_split_pair(g_s2, (size_t)row * K2_H + ng, s0, s1);
                } else if (gate == 2) {
                    float r0 = sigm(v0 + br[ng])     * h[(size_t)row * DH + ng];
                    float r1 = sigm(v1 + br[ng + 1]) * h[(size_t)row * DH + ng + 1];
                    store_split_pair(g_Aht, (size_t)row * K2_HT + ng, r0, r1);
                } else {
                    float2 v = { v0, v1 };
                    *(float2*)(C + (size_t)row * N1 + colg) = v;
                }
            }
        }
    }
}

// ---------------- plain GEMM (Tadd) ------------------------------------------
__global__ __launch_bounds__(NTHR)
void gemm_plain(const __half* __restrict__ A, const __half* __restrict__ W,
                float* __restrict__ C, int K2, int ldc)
{
    extern __shared__ __align__(1024) char smem[];
    const uint32_t sbase = smem_u32(smem);
    const int tid = threadIdx.x;
    const int m0 = blockIdx.y * 128;
    const int n0 = blockIdx.x * 256;

    float acc[2][8][4];
    gemm_core(A, W, K2, m0, n0, sbase, tid, acc);

    const int wid = tid >> 5, lane = tid & 31;
    const int wm = (wid & 3) * 32;
    const int wn = (wid >> 2) * 64;
#pragma unroll
    for (int mi = 0; mi < 2; ++mi) {
        int r0 = m0 + wm + mi * 16 + (lane >> 2);
#pragma unroll
        for (int ni = 0; ni < 8; ++ni) {
            int col = n0 + wn + ni * 8 + (lane & 3) * 2;
            float2 v0 = { acc[mi][ni][0], acc[mi][ni][1] };
            float2 v1 = { acc[mi][ni][2], acc[mi][ni][3] };
            *(float2*)(C + (size_t)r0 * ldc + col)       = v0;
            *(float2*)(C + (size_t)(r0 + 8) * ldc + col) = v1;
        }
    }
}

// ---------------- ht GEMM (rh@W_h^T + x@W_x^T) with fused ew2 epilogue -------
__global__ __launch_bounds__(NTHR)
void gemm_ht_fused(const __half* __restrict__ A, const __half* __restrict__ W,
                   const float* __restrict__ bT, const float* __restrict__ bz,
                   const float* __restrict__ bb, const float* __restrict__ h,
                   float* __restrict__ out)
{
    extern __shared__ __align__(1024) char smem[];
    const uint32_t sbase = smem_u32(smem);
    const int tid = threadIdx.x;
    const int m0 = blockIdx.y * 128;
    const int n0 = blockIdx.x * 256;

    float acc[2][8][4];
    gemm_core(A, W, K2_HT, m0, n0, sbase, tid, acc);

    const int wid = tid >> 5, lane = tid & 31;
    const int wm = (wid & 3) * 32;
    const int wn = (wid >> 2) * 64;

#pragma unroll
    for (int mi = 0; mi < 2; ++mi) {
#pragma unroll
        for (int rr = 0; rr < 2; ++rr) {
            const int row = m0 + wm + mi * 16 + (lane >> 2) + rr * 8;
#pragma unroll
            for (int ni = 0; ni < 8; ++ni) {
                const int ng = n0 + wn + ni * 8 + (lane & 3) * 2;
                const size_t e0 = (size_t)row * DH + ng;
                const size_t c0 = (size_t)row * N1 + ng;
                float v0 = acc[mi][ni][rr * 2 + 0];
                float v1 = acc[mi][ni][rr * 2 + 1];
                float T0 = sigm(g_C1[c0 + 1024] + g_Tadd[e0]     + bT[ng]);
                float T1 = sigm(g_C1[c0 + 1025] + g_Tadd[e0 + 1] + bT[ng + 1]);
                float z0 = sigm(g_C1[c0 + 3072] + bz[ng]);
                float z1 = sigm(g_C1[c0 + 3073] + bz[ng + 1]);
                float t0 = tanhf(v0 + bb[ng]);
                float t1 = tanhf(v1 + bb[ng + 1]);
                float2 o;
                o.x = (1.f - z0) * (T0 * h[e0])     + z0 * t0;
                o.y = (1.f - z1) * (T1 * h[e0 + 1]) + z1 * t1;
                *(float2*)(out + e0) = o;
            }
        }
    }
}

// ---------------- conversion kernels -----------------------------------------
// weights: only hi(W) is ever stored, duplicated into both K-slots
#define NW2  (N1 * 1536)     // stage-1 gate weights (4 gates x [1024 h | 512 x])
#define NWHT (DH * 1536)     // [W_h | W_x]
#define NWS  (DH * DH)       // WTs
__global__ void convW_all(const float* __restrict__ Wsh, const float* __restrict__ Wsx,
                          const float* __restrict__ WTh, const float* __restrict__ WTx,
                          const float* __restrict__ Wrh, const float* __restrict__ Wrx,
                          const float* __restrict__ Wzh, const float* __restrict__ Wzx,
                          const float* __restrict__ Wh,  const float* __restrict__ Wx,
                          const float* __restrict__ WTs)
{
    int idx = blockIdx.x * blockDim.x + threadIdx.x;
    if (idx < NW2) {
        int n = idx / 1536, c = idx - n * 1536;
        int blk = n >> 10, r = n & (DH - 1);
        const float* Ph = (blk == 0) ? Wsh : (blk == 1) ? WTh : (blk == 2) ? Wrh : Wzh;
        const float* Px = (blk == 0) ? Wsx : (blk == 1) ? WTx : (blk == 2) ? Wrx : Wzx;
        size_t rb = (size_t)n * K2_S1;
        if (c < DH) {
            __half hv = __float2half(Ph[(size_t)r * DH + c]);
            g_W2[rb + c] = hv; g_W2[rb + c + 1024] = hv;
        } else {
            int cx = c - DH;
            __half hv = __float2half(Px[(size_t)r * DIN + cx]);
            g_W2[rb + 2048 + cx] = hv; g_W2[rb + 2560 + cx] = hv;
        }
        return;
    }
    idx -= NW2;
    if (idx < NWHT) {
        int n = idx / 1536, c = idx - n * 1536;
        size_t rb = (size_t)n * K2_HT;
        if (c < DH) {
            __half hv = __float2half(Wh[(size_t)n * DH + c]);
            g_Wht[rb + c] = hv; g_Wht[rb + c + 1024] = hv;
        } else {
            int cx = c - DH;
            __half hv = __float2half(Wx[(size_t)n * DIN + cx]);
            g_Wht[rb + 2048 + cx] = hv; g_Wht[rb + 2560 + cx] = hv;
        }
        return;
    }
    idx -= NWHT;
    if (idx < NWS) {
        int n = idx / DH, c = idx - n * DH;
        __half hv = __float2half(WTs[idx]);
        size_t rb = (size_t)n * K2_H;
        g_Ws2[rb + c] = hv; g_Ws2[rb + c + 1024] = hv;
    }
}
#define NW_ALL (NW2 + NWHT + NWS)

// activations: A2 = [h_hi|h_lo|x_hi|x_lo]; A_ht x-part = [.|.|x_hi|x_lo]
#define NACT (B_ * 1536)
__global__ void convAct(const float* __restrict__ h, const float* __restrict__ x)
{
    int idx = blockIdx.x * blockDim.x + threadIdx.x;
    if (idx >= NACT) return;
    int b = idx / 1536, c = idx - b * 1536;
    if (c < DH) {
        __half hi, lo; split2h(h[(size_t)b * DH + c], hi, lo);
        size_t rb = (size_t)b * K2_S1;
        g_A2[rb + c] = hi; g_A2[rb + c + 1024] = lo;
    } else {
        int cx = c - DH;
        __half hi, lo; split2h(x[(size_t)b * DIN + cx], hi, lo);
        size_t rb = (size_t)b * K2_S1;
        g_A2[rb + 2048 + cx] = hi; g_A2[rb + 2560 + cx] = lo;
        size_t hb = (size_t)b * K2_HT;
        g_Aht[hb + 2048 + cx] = hi; g_Aht[hb + 2560 + cx] = lo;
    }
}

// ---------------- launch ----------------------------------------------------
extern "C" void kernel_launch(void* const* d_in, const int* in_sizes, int n_in,
                              void* d_out, int out_size)
{
    const float* x     = (const float*)d_in[0];
    const float* delta = (const float*)d_in[1];
    const float* h     = (const float*)d_in[2];
    const float* W_sh  = (const float*)d_in[3];
    const float* W_sx  = (const float*)d_in[4];
    const float* W_st  = (const float*)d_in[5];
    const float* b_s   = (const float*)d_in[6];
    const float* WTh   = (const float*)d_in[7];
    const float* WTx   = (const float*)d_in[8];
    const float* WTs   = (const float*)d_in[9];
    const float* b_T   = (const float*)d_in[10];
    const float* W_rh  = (const float*)d_in[11];
    const float* W_rx  = (const float*)d_in[12];
    const float* b_r   = (const float*)d_in[13];
    const float* W_zh  = (const float*)d_in[14];
    const float* W_zx  = (const float*)d_in[15];
    const float* b_z   = (const float*)d_in[16];
    const float* W_h   = (const float*)d_in[17];
    const float* W_x   = (const float*)d_in[18];
    const float* b     = (const float*)d_in[19];
    float* out = (float*)d_out;

    cudaFuncSetAttribute(gemm_s1_fused, cudaFuncAttributeMaxDynamicSharedMemorySize, SM_TOT);
    cudaFuncSetAttribute(gemm_plain,    cudaFuncAttributeMaxDynamicSharedMemorySize, SM_TOT);
    cudaFuncSetAttribute(gemm_ht_fused, cudaFuncAttributeMaxDynamicSharedMemorySize, SM_TOT);

    __half *dA2, *dW2, *ds2, *dWs2, *dAht, *dWht;
    float *dC1, *dTadd;
    cudaGetSymbolAddress((void**)&dA2,   g_A2);
    cudaGetSymbolAddress((void**)&dW2,   g_W2);
    cudaGetSymbolAddress((void**)&ds2,   g_s2);
    cudaGetSymbolAddress((void**)&dWs2,  g_Ws2);
    cudaGetSymbolAddress((void**)&dAht,  g_Aht);
    cudaGetSymbolAddress((void**)&dWht,  g_Wht);
    cudaGetSymbolAddress((void**)&dC1,   g_C1);
    cudaGetSymbolAddress((void**)&dTadd, g_Tadd);

    // 1) conversions
    convW_all<<<(NW_ALL + 255) / 256, 256>>>(W_sh, W_sx, WTh, WTx, W_rh, W_rx,
                                             W_zh, W_zx, W_h, W_x, WTs);
    convAct  <<<(NACT + 255) / 256, 256>>>(h, x);

    // 2) stage-1 GEMM + fused ew1 (K=3072) -> g_s2, g_Aht[rh], C1 gates 1&3
    gemm_s1_fused<<<dim3(N1 / 256, B_ / 128), NTHR, SM_TOT>>>(
        dA2, dW2, dC1, delta, W_st, b_s, b_r, h);

    // 3) Tadd = s2 @ Ws2^T  (K=2048)
    gemm_plain<<<dim3(DH / 256, B_ / 128), NTHR, SM_TOT>>>(ds2, dWs2, dTadd, K2_H, DH);

    // 4) ht GEMM (rh@W_h^T + x@W_x^T, K=3072) + fused ew2 -> out
    gemm_ht_fused<<<dim3(DH / 256, B_ / 128), NTHR, SM_TOT>>>(
        dAht, dWht, b_T, b_z, b, h, out);
}

// round 8
// speedup vs baseline: 2.4545x; 1.5278x over previous
#include <cuda_runtime.h>
#include <cstdint>
#include <math.h>

#define B_    16384
#define DIN   512
#define DH    1024

// tf32 single-term K dims
#define KS1 1536    // [h | x]
#define KH  1024    // s
#define KHT 1536    // [rh | x]
#define N1  4096

// ---------------- scratch (tf32-rounded fp32) --------------------------------
__device__ float g_A2 [(size_t)B_ * KS1];
__device__ float g_W2 [(size_t)N1 * KS1];
__device__ float g_s  [(size_t)B_ * KH];
__device__ float g_Ws [(size_t)DH * KH];
__device__ float g_Aht[(size_t)B_ * KHT];
__device__ float g_Wht[(size_t)DH * KHT];
__device__ float g_C1 [(size_t)B_ * N1];    // only gates 1 (T) and 3 (z) written
__device__ float g_Tadd[(size_t)B_ * DH];

// ---------------- helpers ----------------------------------------------------
__device__ __forceinline__ uint32_t smem_u32(const void* p) {
    uint32_t a;
    asm("{ .reg .u64 t; cvta.to.shared.u64 t, %1; cvt.u32.u64 %0, t; }" : "=r"(a) : "l"(p));
    return a;
}
__device__ __forceinline__ void cp16(uint32_t sdst, const void* gsrc) {
    asm volatile("cp.async.cg.shared.global [%0], [%1], 16;" :: "r"(sdst), "l"(gsrc));
}
__device__ __forceinline__ void ldsm4(uint32_t* r, uint32_t addr) {
    asm volatile("ldmatrix.sync.aligned.m8n8.x4.shared.b16 {%0,%1,%2,%3}, [%4];"
                 : "=r"(r[0]), "=r"(r[1]), "=r"(r[2]), "=r"(r[3]) : "r"(addr));
}
__device__ __forceinline__ void mma_tf32(float* d, const uint32_t* a, uint32_t b0, uint32_t b1) {
    asm volatile("mma.sync.aligned.m16n8k8.row.col.f32.tf32.tf32.f32 "
                 "{%0,%1,%2,%3}, {%4,%5,%6,%7}, {%8,%9}, {%0,%1,%2,%3};"
                 : "+f"(d[0]), "+f"(d[1]), "+f"(d[2]), "+f"(d[3])
                 : "r"(a[0]), "r"(a[1]), "r"(a[2]), "r"(a[3]), "r"(b0), "r"(b1));
}
__device__ __forceinline__ float to_tf32(float v) {
    uint32_t u;
    asm("cvt.rna.tf32.f32 %0, %1;" : "=r"(u) : "f"(v));
    return __uint_as_float(u);
}
__device__ __forceinline__ float sigm(float x) { return 1.f / (1.f + expf(-x)); }

// ---------------- GEMM core: 128x256 CTA, 512 thr, 4Mx4N warps, BK=32 tf32 ---
// rows are 32 tf32 = 128B, same swizzle as bf16 path; 3-stage cp.async
#define NTHR 512
#define ST_A_BYTES (128 * 128)
#define ST_B_BYTES (256 * 128)
#define ST_STRIDE  (ST_A_BYTES + ST_B_BYTES)
#define STAGES 3
#define SM_TOT (STAGES * ST_STRIDE)      // 144 KB

__device__ __forceinline__ void load_tile(const float* __restrict__ A,
                                          const float* __restrict__ W,
                                          int K2, int m0, int n0,
                                          uint32_t sbase, int stage, int it, int tid)
{
    const size_t k0 = (size_t)it * 32;               // 32 tf32 per iter
    const uint32_t sA = sbase + stage * ST_STRIDE;
    const uint32_t sB = sA + ST_A_BYTES;
#pragma unroll
    for (int j = 0; j < 6; ++j) {
        int f = tid + j * NTHR;
        if (f < 1024) {
            int row = f >> 3, c = f & 7;
            cp16(sA + row * 128 + ((c ^ (row & 7)) << 4),
                 A + (size_t)(m0 + row) * K2 + k0 + c * 4);
        } else {
            int f2 = f - 1024, row = f2 >> 3, c = f2 & 7;
            cp16(sB + row * 128 + ((c ^ (row & 7)) << 4),
                 W + (size_t)(n0 + row) * K2 + k0 + c * 4);
        }
    }
}

__device__ __forceinline__ void gemm_core(const float* __restrict__ A,
                                          const float* __restrict__ W,
                                          int K2, int m0, int n0,
                                          uint32_t sbase, int tid,
                                          float acc[2][8][4])
{
    const int wid = tid >> 5, lane = tid & 31;
    const int wm = (wid & 3) * 32;
    const int wn = (wid >> 2) * 64;
    const int T  = K2 >> 5;

#pragma unroll
    for (int i = 0; i < 2; i++)
#pragma unroll
        for (int j = 0; j < 8; j++)
#pragma unroll
            for (int k = 0; k < 4; k++) acc[i][j][k] = 0.f;

#pragma unroll
    for (int it = 0; it < STAGES - 1; ++it) {
        load_tile(A, W, K2, m0, n0, sbase, it, it, tid);
        asm volatile("cp.async.commit_group;" ::: "memory");
    }

    const int la = lane & 15;
    const int lk = lane >> 4;

    for (int it = 0; it < T; ++it) {
        asm volatile("cp.async.wait_group 1;" ::: "memory");
        __syncthreads();

        int pf = it + STAGES - 1;
        if (pf < T) load_tile(A, W, K2, m0, n0, sbase, pf % STAGES, pf, tid);
        asm volatile("cp.async.commit_group;" ::: "memory");

        const uint32_t aA = sbase + (it % STAGES) * ST_STRIDE;
        const uint32_t aB = aA + ST_A_BYTES;

#pragma unroll
        for (int ks = 0; ks < 4; ++ks) {          // 4 x k8 steps
            const int c = ks * 2 + lk;            // 16B chunk: lo/hi half of k8
            uint32_t af[2][4];
#pragma unroll
            for (int mi = 0; mi < 2; ++mi) {
                int row = wm + mi * 16 + la;
                ldsm4(af[mi], aA + row * 128 + ((c ^ (row & 7)) << 4));
            }
            uint32_t bfr[4][4];
#pragma unroll
            for (int nb = 0; nb < 4; ++nb) {
                int row = wn + nb * 16 + la;
                ldsm4(bfr[nb], aB + row * 128 + ((c ^ (row & 7)) << 4));
            }
#pragma unroll
            for (int mi = 0; mi < 2; ++mi)
#pragma unroll
                for (int nb = 0; nb < 4; ++nb) {
                    mma_tf32(acc[mi][nb * 2 + 0], af[mi], bfr[nb][0], bfr[nb][2]);
                    mma_tf32(acc[mi][nb * 2 + 1], af[mi], bfr[nb][1], bfr[nb][3]);
                }
        }
    }
}

// ---------------- stage-1 GEMM with fused ew1 epilogue ----------------------
// gate = n0>>10: 0 -> s (g_s), 1 -> C1, 2 -> r*h (g_Aht[0:1024]), 3 -> C1
__global__ __launch_bounds__(NTHR)
void gemm_s1_fused(const float* __restrict__ A, const float* __restrict__ W,
                   float* __restrict__ C,
                   const float* __restrict__ delta, const float* __restrict__ Wst,
                   const float* __restrict__ bs, const float* __restrict__ br,
                   const float* __restrict__ h)
{
    extern __shared__ __align__(1024) char smem[];
    const uint32_t sbase = smem_u32(smem);
    const int tid = threadIdx.x;
    const int m0 = blockIdx.y * 128;
    const int n0 = blockIdx.x * 256;

    float acc[2][8][4];
    gemm_core(A, W, KS1, m0, n0, sbase, tid, acc);

    const int wid = tid >> 5, lane = tid & 31;
    const int wm = (wid & 3) * 32;
    const int wn = (wid >> 2) * 64;
    const int gate = n0 >> 10;

#pragma unroll
    for (int mi = 0; mi < 2; ++mi) {
#pragma unroll
        for (int rr = 0; rr < 2; ++rr) {
            const int row = m0 + wm + mi * 16 + (lane >> 2) + rr * 8;
            const float dv = (gate == 0) ? delta[row] : 0.f;
#pragma unroll
            for (int ni = 0; ni < 8; ++ni) {
                const int colg = n0 + wn + ni * 8 + (lane & 3) * 2;
                const int ng   = colg & 1023;
                float v0 = acc[mi][ni][rr * 2 + 0];
                float v1 = acc[mi][ni][rr * 2 + 1];
                if (gate == 0) {
                    float2 sv;
                    sv.x = to_tf32(tanhf(v0 + dv * Wst[ng]     + bs[ng]));
                    sv.y = to_tf32(tanhf(v1 + dv * Wst[ng + 1] + bs[ng + 1]));
                    *(float2*)(g_s + (size_t)row * KH + ng) = sv;
                } else if (gate == 2) {
                    float2 rv;
                    rv.x = to_tf32(sigm(v0 + br[ng])     * h[(size_t)row * DH + ng]);
                    rv.y = to_tf32(sigm(v1 + br[ng + 1]) * h[(size_t)row * DH + ng + 1]);
                    *(float2*)(g_Aht + (size_t)row * KHT + ng) = rv;
                } else {
                    float2 v = { v0, v1 };
                    *(float2*)(C + (size_t)row * N1 + colg) = v;
                }
            }
        }
    }
}

// ---------------- plain GEMM (Tadd) ------------------------------------------
__global__ __launch_bounds__(NTHR)
void gemm_plain(const float* __restrict__ A, const float* __restrict__ W,
                float* __restrict__ C, int K2, int ldc)
{
    extern __shared__ __align__(1024) char smem[];
    const uint32_t sbase = smem_u32(smem);
    const int tid = threadIdx.x;
    const int m0 = blockIdx.y * 128;
    const int n0 = blockIdx.x * 256;

    float acc[2][8][4];
    gemm_core(A, W, K2, m0, n0, sbase, tid, acc);

    const int wid = tid >> 5, lane = tid & 31;
    const int wm = (wid & 3) * 32;
    const int wn = (wid >> 2) * 64;
#pragma unroll
    for (int mi = 0; mi < 2; ++mi) {
        int r0 = m0 + wm + mi * 16 + (lane >> 2);
#pragma unroll
        for (int ni = 0; ni < 8; ++ni) {
            int col = n0 + wn + ni * 8 + (lane & 3) * 2;
            float2 v0 = { acc[mi][ni][0], acc[mi][ni][1] };
            float2 v1 = { acc[mi][ni][2], acc[mi][ni][3] };
            *(float2*)(C + (size_t)r0 * ldc + col)       = v0;
            *(float2*)(C + (size_t)(r0 + 8) * ldc + col) = v1;
        }
    }
}

// ---------------- ht GEMM (rh@W_h^T + x@W_x^T) with fused ew2 epilogue -------
__global__ __launch_bounds__(NTHR)
void gemm_ht_fused(const float* __restrict__ A, const float* __restrict__ W,
                   const float* __restrict__ bT, const float* __restrict__ bz,
                   const float* __restrict__ bb, const float* __restrict__ h,
                   float* __restrict__ out)
{
    extern __shared__ __align__(1024) char smem[];
    const uint32_t sbase = smem_u32(smem);
    const int tid = threadIdx.x;
    const int m0 = blockIdx.y * 128;
    const int n0 = blockIdx.x * 256;

    float acc[2][8][4];
    gemm_core(A, W, KHT, m0, n0, sbase, tid, acc);

    const int wid = tid >> 5, lane = tid & 31;
    const int wm = (wid & 3) * 32;
    const int wn = (wid >> 2) * 64;

#pragma unroll
    for (int mi = 0; mi < 2; ++mi) {
#pragma unroll
        for (int rr = 0; rr < 2; ++rr) {
            const int row = m0 + wm + mi * 16 + (lane >> 2) + rr * 8;
#pragma unroll
            for (int ni = 0; ni < 8; ++ni) {
                const int ng = n0 + wn + ni * 8 + (lane & 3) * 2;
                const size_t e0 = (size_t)row * DH + ng;
                const size_t c0 = (size_t)row * N1 + ng;
                float v0 = acc[mi][ni][rr * 2 + 0];
                float v1 = acc[mi][ni][rr * 2 + 1];
                float T0 = sigm(g_C1[c0 + 1024] + g_Tadd[e0]     + bT[ng]);
                float T1 = sigm(g_C1[c0 + 1025] + g_Tadd[e0 + 1] + bT[ng + 1]);
                float z0 = sigm(g_C1[c0 + 3072] + bz[ng]);
                float z1 = sigm(g_C1[c0 + 3073] + bz[ng + 1]);
                float t0 = tanhf(v0 + bb[ng]);
                float t1 = tanhf(v1 + bb[ng + 1]);
                float2 o;
                o.x = (1.f - z0) * (T0 * h[e0])     + z0 * t0;
                o.y = (1.f - z1) * (T1 * h[e0 + 1]) + z1 * t1;
                *(float2*)(out + e0) = o;
            }
        }
    }
}

// ---------------- conversion kernels (tf32 rounding + concat) ----------------
#define NW2  (N1 * KS1)      // stage-1 gate weights
#define NWHT (DH * KHT)      // [W_h | W_x]
#define NWS  (DH * KH)       // WTs
__global__ void convW_all(const float* __restrict__ Wsh, const float* __restrict__ Wsx,
                          const float* __restrict__ WTh, const float* __restrict__ WTx,
                          const float* __restrict__ Wrh, const float* __restrict__ Wrx,
                          const float* __restrict__ Wzh, const float* __restrict__ Wzx,
                          const float* __restrict__ Wh,  const float* __restrict__ Wx,
                          const float* __restrict__ WTs)
{
    int idx = blockIdx.x * blockDim.x + threadIdx.x;
    if (idx < NW2) {
        int n = idx / KS1, c = idx - n * KS1;
        int blk = n >> 10, r = n & (DH - 1);
        const float* Ph = (blk == 0) ? Wsh : (blk == 1) ? WTh : (blk == 2) ? Wrh : Wzh;
        const float* Px = (blk == 0) ? Wsx : (blk == 1) ? WTx : (blk == 2) ? Wrx : Wzx;
        float v = (c < DH) ? Ph[(size_t)r * DH + c] : Px[(size_t)r * DIN + c - DH];
        g_W2[idx] = to_tf32(v);
        return;
    }
    idx -= NW2;
    if (idx < NWHT) {
        int n = idx / KHT, c = idx - n * KHT;
        float v = (c < DH) ? Wh[(size_t)n * DH + c] : Wx[(size_t)n * DIN + c - DH];
        g_Wht[idx] = to_tf32(v);
        return;
    }
    idx -= NWHT;
    if (idx < NWS) {
        g_Ws[idx] = to_tf32(WTs[idx]);
    }
}
#define NW_ALL (NW2 + NWHT + NWS)

// activations: A2 = [h | x] tf32; A_ht x-part
#define NACT (B_ * KS1)
__global__ void convAct(const float* __restrict__ h, const float* __restrict__ x)
{
    int idx = blockIdx.x * blockDim.x + threadIdx.x;
    if (idx >= NACT) return;
    int b = idx / KS1, c = idx - b * KS1;
    if (c < DH) {
        g_A2[idx] = to_tf32(h[(size_t)b * DH + c]);
    } else {
        float xv = to_tf32(x[(size_t)b * DIN + c - DH]);
        g_A2[idx] = xv;
        g_Aht[(size_t)b * KHT + c] = xv;       // same offset layout [rh | x]
    }
}

// ---------------- launch ----------------------------------------------------
extern "C" void kernel_launch(void* const* d_in, const int* in_sizes, int n_in,
                              void* d_out, int out_size)
{
    const float* x     = (const float*)d_in[0];
    const float* delta = (const float*)d_in[1];
    const float* h     = (const float*)d_in[2];
    const float* W_sh  = (const float*)d_in[3];
    const float* W_sx  = (const float*)d_in[4];
    const float* W_st  = (const float*)d_in[5];
    const float* b_s   = (const float*)d_in[6];
    const float* WTh   = (const float*)d_in[7];
    const float* WTx   = (const float*)d_in[8];
    const float* WTs   = (const float*)d_in[9];
    const float* b_T   = (const float*)d_in[10];
    const float* W_rh  = (const float*)d_in[11];
    const float* W_rx  = (const float*)d_in[12];
    const float* b_r   = (const float*)d_in[13];
    const float* W_zh  = (const float*)d_in[14];
    const float* W_zx  = (const float*)d_in[15];
    const float* b_z   = (const float*)d_in[16];
    const float* W_h   = (const float*)d_in[17];
    const float* W_x   = (const float*)d_in[18];
    const float* b     = (const float*)d_in[19];
    float* out = (float*)d_out;

    cudaFuncSetAttribute(gemm_s1_fused, cudaFuncAttributeMaxDynamicSharedMemorySize, SM_TOT);
    cudaFuncSetAttribute(gemm_plain,    cudaFuncAttributeMaxDynamicSharedMemorySize, SM_TOT);
    cudaFuncSetAttribute(gemm_ht_fused, cudaFuncAttributeMaxDynamicSharedMemorySize, SM_TOT);

    float *dA2, *dW2, *ds, *dWs, *dAht, *dWht, *dC1, *dTadd;
    cudaGetSymbolAddress((void**)&dA2,   g_A2);
    cudaGetSymbolAddress((void**)&dW2,   g_W2);
    cudaGetSymbolAddress((void**)&ds,    g_s);
    cudaGetSymbolAddress((void**)&dWs,   g_Ws);
    cudaGetSymbolAddress((void**)&dAht,  g_Aht);
    cudaGetSymbolAddress((void**)&dWht,  g_Wht);
    cudaGetSymbolAddress((void**)&dC1,   g_C1);
    cudaGetSymbolAddress((void**)&dTadd, g_Tadd);

    // 1) tf32 rounding + concat
    convW_all<<<(NW_ALL + 255) / 256, 256>>>(W_sh, W_sx, WTh, WTx, W_rh, W_rx,
                                             W_zh, W_zx, W_h, W_x, WTs);
    convAct  <<<(NACT + 255) / 256, 256>>>(h, x);

    // 2) stage-1 GEMM + fused ew1 (K=1536) -> g_s, g_Aht[rh], C1 gates 1&3
    gemm_s1_fused<<<dim3(N1 / 256, B_ / 128), NTHR, SM_TOT>>>(
        dA2, dW2, dC1, delta, W_st, b_s, b_r, h);

    // 3) Tadd = s @ WTs^T  (K=1024)
    gemm_plain<<<dim3(DH / 256, B_ / 128), NTHR, SM_TOT>>>(ds, dWs, dTadd, KH, DH);

    // 4) ht GEMM (rh@W_h^T + x@W_x^T, K=1536) + fused ew2 -> out
    gemm_ht_fused<<<dim3(DH / 256, B_ / 128), NTHR, SM_TOT>>>(
        dAht, dWht, b_T, b_z, b, h, out);
}

// round 9
// speedup vs baseline: 2.8152x; 1.1469x over previous
#include <cuda_runtime.h>
#include <cstdint>
#include <math.h>

#define B_    16384
#define DIN   512
#define DH    1024

// tf32 single-term K dims
#define KS1 1536    // [h | x]
#define KH  1024    // s
#define KHT 1536    // [rh | x]
#define N1  4096

// ---------------- scratch (tf32-rounded fp32) --------------------------------
__device__ float g_A2 [(size_t)B_ * KS1];
__device__ float g_W2 [(size_t)N1 * KS1];
__device__ float g_s  [(size_t)B_ * KH];
__device__ float g_Ws [(size_t)DH * KH];
__device__ float g_Aht[(size_t)B_ * KHT];
__device__ float g_Wht[(size_t)DH * KHT];
__device__ float g_C1 [(size_t)B_ * N1];    // only gates 1 (T) and 3 (z) written
__device__ float g_Tadd[(size_t)B_ * DH];

// ---------------- helpers ----------------------------------------------------
__device__ __forceinline__ uint32_t smem_u32(const void* p) {
    uint32_t a;
    asm("{ .reg .u64 t; cvta.to.shared.u64 t, %1; cvt.u32.u64 %0, t; }" : "=r"(a) : "l"(p));
    return a;
}
__device__ __forceinline__ void cp16(uint32_t sdst, const void* gsrc) {
    asm volatile("cp.async.cg.shared.global [%0], [%1], 16;" :: "r"(sdst), "l"(gsrc));
}
__device__ __forceinline__ void ldsm4(uint32_t* r, uint32_t addr) {
    asm volatile("ldmatrix.sync.aligned.m8n8.x4.shared.b16 {%0,%1,%2,%3}, [%4];"
                 : "=r"(r[0]), "=r"(r[1]), "=r"(r[2]), "=r"(r[3]) : "r"(addr));
}
__device__ __forceinline__ void mma_tf32(float* d, const uint32_t* a, uint32_t b0, uint32_t b1) {
    asm volatile("mma.sync.aligned.m16n8k8.row.col.f32.tf32.tf32.f32 "
                 "{%0,%1,%2,%3}, {%4,%5,%6,%7}, {%8,%9}, {%0,%1,%2,%3};"
                 : "+f"(d[0]), "+f"(d[1]), "+f"(d[2]), "+f"(d[3])
                 : "r"(a[0]), "r"(a[1]), "r"(a[2]), "r"(a[3]), "r"(b0), "r"(b1));
}
__device__ __forceinline__ float to_tf32(float v) {
    uint32_t u;
    asm("cvt.rna.tf32.f32 %0, %1;" : "=r"(u) : "f"(v));
    return __uint_as_float(u);
}
__device__ __forceinline__ float sigm(float x) { return 1.f / (1.f + expf(-x)); }

// ---------------- GEMM core: 128x128 CTA, 256 thr, 8 warps 4Mx2N, BK=32 ------
// warp tile 32x64 (same inner loop as before); 3-stage cp.async; 2 CTAs/SM
#define NTHR 256
#define ST_A_BYTES (128 * 128)
#define ST_B_BYTES (128 * 128)
#define ST_STRIDE  (ST_A_BYTES + ST_B_BYTES)   // 32 KB
#define STAGES 3
#define SM_TOT (STAGES * ST_STRIDE)            // 96 KB

__device__ __forceinline__ void load_tile(const float* __restrict__ A,
                                          const float* __restrict__ W,
                                          int K2, int m0, int n0,
                                          uint32_t sbase, int stage, int it, int tid)
{
    const size_t k0 = (size_t)it * 32;               // 32 tf32 per iter
    const uint32_t sA = sbase + stage * ST_STRIDE;
    const uint32_t sB = sA + ST_A_BYTES;
#pragma unroll
    for (int j = 0; j < 8; ++j) {
        int f = tid + j * NTHR;                      // 0..2047
        if (f < 1024) {
            int row = f >> 3, c = f & 7;
            cp16(sA + row * 128 + ((c ^ (row & 7)) << 4),
                 A + (size_t)(m0 + row) * K2 + k0 + c * 4);
        } else {
            int f2 = f - 1024, row = f2 >> 3, c = f2 & 7;
            cp16(sB + row * 128 + ((c ^ (row & 7)) << 4),
                 W + (size_t)(n0 + row) * K2 + k0 + c * 4);
        }
    }
}

__device__ __forceinline__ void gemm_core(const float* __restrict__ A,
                                          const float* __restrict__ W,
                                          int K2, int m0, int n0,
                                          uint32_t sbase, int tid,
                                          float acc[2][8][4])
{
    const int wid = tid >> 5, lane = tid & 31;
    const int wm = (wid & 3) * 32;          // 4 warps in M
    const int wn = (wid >> 2) * 64;         // 2 warps in N
    const int T  = K2 >> 5;

#pragma unroll
    for (int i = 0; i < 2; i++)
#pragma unroll
        for (int j = 0; j < 8; j++)
#pragma unroll
            for (int k = 0; k < 4; k++) acc[i][j][k] = 0.f;

#pragma unroll
    for (int it = 0; it < STAGES - 1; ++it) {
        load_tile(A, W, K2, m0, n0, sbase, it, it, tid);
        asm volatile("cp.async.commit_group;" ::: "memory");
    }

    const int la = lane & 15;
    const int lk = lane >> 4;

    for (int it = 0; it < T; ++it) {
        asm volatile("cp.async.wait_group 1;" ::: "memory");
        __syncthreads();

        int pf = it + STAGES - 1;
        if (pf < T) load_tile(A, W, K2, m0, n0, sbase, pf % STAGES, pf, tid);
        asm volatile("cp.async.commit_group;" ::: "memory");

        const uint32_t aA = sbase + (it % STAGES) * ST_STRIDE;
        const uint32_t aB = aA + ST_A_BYTES;

#pragma unroll
        for (int ks = 0; ks < 4; ++ks) {          // 4 x k8 steps
            const int c = ks * 2 + lk;
            uint32_t af[2][4];
#pragma unroll
            for (int mi = 0; mi < 2; ++mi) {
                int row = wm + mi * 16 + la;
                ldsm4(af[mi], aA + row * 128 + ((c ^ (row & 7)) << 4));
            }
            uint32_t bfr[4][4];
#pragma unroll
            for (int nb = 0; nb < 4; ++nb) {
                int row = wn + nb * 16 + la;
                ldsm4(bfr[nb], aB + row * 128 + ((c ^ (row & 7)) << 4));
            }
#pragma unroll
            for (int mi = 0; mi < 2; ++mi)
#pragma unroll
                for (int nb = 0; nb < 4; ++nb) {
                    mma_tf32(acc[mi][nb * 2 + 0], af[mi], bfr[nb][0], bfr[nb][2]);
                    mma_tf32(acc[mi][nb * 2 + 1], af[mi], bfr[nb][1], bfr[nb][3]);
                }
        }
    }
}

// ---------------- stage-1 GEMM with fused ew1 epilogue ----------------------
// gate = n0>>10: 0 -> s (g_s), 1 -> C1, 2 -> r*h (g_Aht[0:1024]), 3 -> C1
__global__ __launch_bounds__(NTHR, 2)
void gemm_s1_fused(const float* __restrict__ A, const float* __restrict__ W,
                   float* __restrict__ C,
                   const float* __restrict__ delta, const float* __restrict__ Wst,
                   const float* __restrict__ bs, const float* __restrict__ br,
                   const float* __restrict__ h)
{
    extern __shared__ __align__(1024) char smem[];
    const uint32_t sbase = smem_u32(smem);
    const int tid = threadIdx.x;
    const int m0 = blockIdx.y * 128;
    const int n0 = blockIdx.x * 128;

    float acc[2][8][4];
    gemm_core(A, W, KS1, m0, n0, sbase, tid, acc);

    const int wid = tid >> 5, lane = tid & 31;
    const int wm = (wid & 3) * 32;
    const int wn = (wid >> 2) * 64;
    const int gate = n0 >> 10;

#pragma unroll
    for (int mi = 0; mi < 2; ++mi) {
#pragma unroll
        for (int rr = 0; rr < 2; ++rr) {
            const int row = m0 + wm + mi * 16 + (lane >> 2) + rr * 8;
            const float dv = (gate == 0) ? delta[row] : 0.f;
#pragma unroll
            for (int ni = 0; ni < 8; ++ni) {
                const int colg = n0 + wn + ni * 8 + (lane & 3) * 2;
                const int ng   = colg & 1023;
                float v0 = acc[mi][ni][rr * 2 + 0];
                float v1 = acc[mi][ni][rr * 2 + 1];
                if (gate == 0) {
                    float2 sv;
                    sv.x = to_tf32(tanhf(v0 + dv * Wst[ng]     + bs[ng]));
                    sv.y = to_tf32(tanhf(v1 + dv * Wst[ng + 1] + bs[ng + 1]));
                    *(float2*)(g_s + (size_t)row * KH + ng) = sv;
                } else if (gate == 2) {
                    float2 rv;
                    rv.x = to_tf32(sigm(v0 + br[ng])     * h[(size_t)row * DH + ng]);
                    rv.y = to_tf32(sigm(v1 + br[ng + 1]) * h[(size_t)row * DH + ng + 1]);
                    *(float2*)(g_Aht + (size_t)row * KHT + ng) = rv;
                } else {
                    float2 v = { v0, v1 };
                    *(float2*)(C + (size_t)row * N1 + colg) = v;
                }
            }
        }
    }
}

// ---------------- plain GEMM (Tadd) ------------------------------------------
__global__ __launch_bounds__(NTHR, 2)
void gemm_plain(const float* __restrict__ A, const float* __restrict__ W,
                float* __restrict__ C, int K2, int ldc)
{
    extern __shared__ __align__(1024) char smem[];
    const uint32_t sbase = smem_u32(smem);
    const int tid = threadIdx.x;
    const int m0 = blockIdx.y * 128;
    const int n0 = blockIdx.x * 128;

    float acc[2][8][4];
    gemm_core(A, W, K2, m0, n0, sbase, tid, acc);

    const int wid = tid >> 5, lane = tid & 31;
    const int wm = (wid & 3) * 32;
    const int wn = (wid >> 2) * 64;
#pragma unroll
    for (int mi = 0; mi < 2; ++mi) {
        int r0 = m0 + wm + mi * 16 + (lane >> 2);
#pragma unroll
        for (int ni = 0; ni < 8; ++ni) {
            int col = n0 + wn + ni * 8 + (lane & 3) * 2;
            float2 v0 = { acc[mi][ni][0], acc[mi][ni][1] };
            float2 v1 = { acc[mi][ni][2], acc[mi][ni][3] };
            *(float2*)(C + (size_t)r0 * ldc + col)       = v0;
            *(float2*)(C + (size_t)(r0 + 8) * ldc + col) = v1;
        }
    }
}

// ---------------- ht GEMM (rh@W_h^T + x@W_x^T) with fused ew2 epilogue -------
__global__ __launch_bounds__(NTHR, 2)
void gemm_ht_fused(const float* __restrict__ A, const float* __restrict__ W,
                   const float* __restrict__ bT, const float* __restrict__ bz,
                   const float* __restrict__ bb, const float* __restrict__ h,
                   float* __restrict__ out)
{
    extern __shared__ __align__(1024) char smem[];
    const uint32_t sbase = smem_u32(smem);
    const int tid = threadIdx.x;
    const int m0 = blockIdx.y * 128;
    const int n0 = blockIdx.x * 128;

    float acc[2][8][4];
    gemm_core(A, W, KHT, m0, n0, sbase, tid, acc);

    const int wid = tid >> 5, lane = tid & 31;
    const int wm = (wid & 3) * 32;
    const int wn = (wid >> 2) * 64;

#pragma unroll
    for (int mi = 0; mi < 2; ++mi) {
#pragma unroll
        for (int rr = 0; rr < 2; ++rr) {
            const int row = m0 + wm + mi * 16 + (lane >> 2) + rr * 8;
#pragma unroll
            for (int ni = 0; ni < 8; ++ni) {
                const int ng = n0 + wn + ni * 8 + (lane & 3) * 2;
                const size_t e0 = (size_t)row * DH + ng;
                const size_t c0 = (size_t)row * N1 + ng;
                float v0 = acc[mi][ni][rr * 2 + 0];
                float v1 = acc[mi][ni][rr * 2 + 1];
                float T0 = sigm(g_C1[c0 + 1024] + g_Tadd[e0]     + bT[ng]);
                float T1 = sigm(g_C1[c0 + 1025] + g_Tadd[e0 + 1] + bT[ng + 1]);
                float z0 = sigm(g_C1[c0 + 3072] + bz[ng]);
                float z1 = sigm(g_C1[c0 + 3073] + bz[ng + 1]);
                float t0 = tanhf(v0 + bb[ng]);
                float t1 = tanhf(v1 + bb[ng + 1]);
                float2 o;
                o.x = (1.f - z0) * (T0 * h[e0])     + z0 * t0;
                o.y = (1.f - z1) * (T1 * h[e0 + 1]) + z1 * t1;
                *(float2*)(out + e0) = o;
            }
        }
    }
}

// ---------------- conversion kernels (tf32 rounding + concat) ----------------
#define NW2  (N1 * KS1)
#define NWHT (DH * KHT)
#define NWS  (DH * KH)
__global__ void convW_all(const float* __restrict__ Wsh, const float* __restrict__ Wsx,
                          const float* __restrict__ WTh, const float* __restrict__ WTx,
                          const float* __restrict__ Wrh, const float* __restrict__ Wrx,
                          const float* __restrict__ Wzh, const float* __restrict__ Wzx,
                          const float* __restrict__ Wh,  const float* __restrict__ Wx,
                          const float* __restrict__ WTs)
{
    int idx = blockIdx.x * blockDim.x + threadIdx.x;
    if (idx < NW2) {
        int n = idx / KS1, c = idx - n * KS1;
        int blk = n >> 10, r = n & (DH - 1);
        const float* Ph = (blk == 0) ? Wsh : (blk == 1) ? WTh : (blk == 2) ? Wrh : Wzh;
        const float* Px = (blk == 0) ? Wsx : (blk == 1) ? WTx : (blk == 2) ? Wrx : Wzx;
        float v = (c < DH) ? Ph[(size_t)r * DH + c] : Px[(size_t)r * DIN + c - DH];
        g_W2[idx] = to_tf32(v);
        return;
    }
    idx -= NW2;
    if (idx < NWHT) {
        int n = idx / KHT, c = idx - n * KHT;
        float v = (c < DH) ? Wh[(size_t)n * DH + c] : Wx[(size_t)n * DIN + c - DH];
        g_Wht[idx] = to_tf32(v);
        return;
    }
    idx -= NWHT;
    if (idx < NWS) {
        g_Ws[idx] = to_tf32(WTs[idx]);
    }
}
#define NW_ALL (NW2 + NWHT + NWS)

#define NACT (B_ * KS1)
__global__ void convAct(const float* __restrict__ h, const float* __restrict__ x)
{
    int idx = blockIdx.x * blockDim.x + threadIdx.x;
    if (idx >= NACT) return;
    int b = idx / KS1, c = idx - b * KS1;
    if (c < DH) {
        g_A2[idx] = to_tf32(h[(size_t)b * DH + c]);
    } else {
        float xv = to_tf32(x[(size_t)b * DIN + c - DH]);
        g_A2[idx] = xv;
        g_Aht[(size_t)b * KHT + c] = xv;
    }
}

// ---------------- launch ----------------------------------------------------
extern "C" void kernel_launch(void* const* d_in, const int* in_sizes, int n_in,
                              void* d_out, int out_size)
{
    const float* x     = (const float*)d_in[0];
    const float* delta = (const float*)d_in[1];
    const float* h     = (const float*)d_in[2];
    const float* W_sh  = (const float*)d_in[3];
    const float* W_sx  = (const float*)d_in[4];
    const float* W_st  = (const float*)d_in[5];
    const float* b_s   = (const float*)d_in[6];
    const float* WTh   = (const float*)d_in[7];
    const float* WTx   = (const float*)d_in[8];
    const float* WTs   = (const float*)d_in[9];
    const float* b_T   = (const float*)d_in[10];
    const float* W_rh  = (const float*)d_in[11];
    const float* W_rx  = (const float*)d_in[12];
    const float* b_r   = (const float*)d_in[13];
    const float* W_zh  = (const float*)d_in[14];
    const float* W_zx  = (const float*)d_in[15];
    const float* b_z   = (const float*)d_in[16];
    const float* W_h   = (const float*)d_in[17];
    const float* W_x   = (const float*)d_in[18];
    const float* b     = (const float*)d_in[19];
    float* out = (float*)d_out;

    cudaFuncSetAttribute(gemm_s1_fused, cudaFuncAttributeMaxDynamicSharedMemorySize, SM_TOT);
    cudaFuncSetAttribute(gemm_plain,    cudaFuncAttributeMaxDynamicSharedMemorySize, SM_TOT);
    cudaFuncSetAttribute(gemm_ht_fused, cudaFuncAttributeMaxDynamicSharedMemorySize, SM_TOT);

    float *dA2, *dW2, *ds, *dWs, *dAht, *dWht, *dC1, *dTadd;
    cudaGetSymbolAddress((void**)&dA2,   g_A2);
    cudaGetSymbolAddress((void**)&dW2,   g_W2);
    cudaGetSymbolAddress((void**)&ds,    g_s);
    cudaGetSymbolAddress((void**)&dWs,   g_Ws);
    cudaGetSymbolAddress((void**)&dAht,  g_Aht);
    cudaGetSymbolAddress((void**)&dWht,  g_Wht);
    cudaGetSymbolAddress((void**)&dC1,   g_C1);
    cudaGetSymbolAddress((void**)&dTadd, g_Tadd);

    // 1) tf32 rounding + concat
    convW_all<<<(NW_ALL + 255) / 256, 256>>>(W_sh, W_sx, WTh, WTx, W_rh, W_rx,
                                             W_zh, W_zx, W_h, W_x, WTs);
    convAct  <<<(NACT + 255) / 256, 256>>>(h, x);

    // 2) stage-1 GEMM + fused ew1 (K=1536) -> g_s, g_Aht[rh], C1 gates 1&3
    gemm_s1_fused<<<dim3(N1 / 128, B_ / 128), NTHR, SM_TOT>>>(
        dA2, dW2, dC1, delta, W_st, b_s, b_r, h);

    // 3) Tadd = s @ WTs^T  (K=1024)
    gemm_plain<<<dim3(DH / 128, B_ / 128), NTHR, SM_TOT>>>(ds, dWs, dTadd, KH, DH);

    // 4) ht GEMM (rh@W_h^T + x@W_x^T, K=1536) + fused ew2 -> out
    gemm_ht_fused<<<dim3(DH / 128, B_ / 128), NTHR, SM_TOT>>>(
        dAht, dWht, b_T, b_z, b, h, out);
}